// round 9
// baseline (speedup 1.0000x reference)
#include <cuda_runtime.h>

// DynamicHead: per-sample grouped 1x1 conv (KERNEL_SIZE=1, PAD=0).
// f:      [B=8, C=400, H=128, W=128] fp32   (210 MB, read exactly once)
// kernel: [B=8, N=50, CPG=8]         fp32   (12.8 KB)
// out:    [B=8, N=50, H=128, W=128]  fp32   (26 MB, written once)
//
// R8: extend the R7 page-locality win. 16 CTAs cooperate per (b,n) group
// (74 groups x 16 = 1184 CTAs = exactly one resident wave). Concurrent
// input planes drop 1216 -> 592, halving the hot DRAM-page working set;
// each group burns through its 512KB 8-plane region in a tighter window.
// Per-thread structure identical to proven-best: 8 independent LDG.128
// (MLP=8), default cache policy, warp-uniform L1-broadcast weights.

#define N_      50
#define HW4_    4096                      // 128*128/4 float4 per plane
#define BN_     400
#define TPB_    256
#define GRPW_   16                        // sub-CTAs per group
#define NGRP_   74                        // 74*16 = 1184 CTAs (one wave)

__global__ __launch_bounds__(TPB_)
void dynhead_1x1_stripe16(const float4* __restrict__ f4,
                          const float* __restrict__ kern,
                          float4* __restrict__ o4) {
    const int g   = blockIdx.x >> 4;        // group id (0..73)
    const int sub = blockIdx.x & (GRPW_-1); // 0..15 within group

    // sub-CTA s owns contiguous pos range [s*256, (s+1)*256) of each plane.
    const int pos = sub * TPB_ + threadIdx.x;

    for (int bn = g; bn < BN_; bn += NGRP_) {
        const int b = bn / N_;
        const int n = bn - b * N_;

        // 8 group weights: warp-uniform, L1 broadcast.
        const float* kp = kern + bn * 8;
        const float w0 = __ldg(kp + 0), w1 = __ldg(kp + 1);
        const float w2 = __ldg(kp + 2), w3 = __ldg(kp + 3);
        const float w4 = __ldg(kp + 4), w5 = __ldg(kp + 5);
        const float w6 = __ldg(kp + 6), w7 = __ldg(kp + 7);

        const float4* __restrict__ fp = f4 + ((b * 400 + n * 8) << 12) + pos;
        float4* __restrict__ op = o4 + (bn << 12) + pos;

        const float4 v0 = fp[0 * HW4_];
        const float4 v1 = fp[1 * HW4_];
        const float4 v2 = fp[2 * HW4_];
        const float4 v3 = fp[3 * HW4_];
        const float4 v4 = fp[4 * HW4_];
        const float4 v5 = fp[5 * HW4_];
        const float4 v6 = fp[6 * HW4_];
        const float4 v7 = fp[7 * HW4_];

        float4 acc;
        acc.x = v0.x * w0; acc.y = v0.y * w0; acc.z = v0.z * w0; acc.w = v0.w * w0;
        acc.x = fmaf(w1, v1.x, acc.x); acc.y = fmaf(w1, v1.y, acc.y);
        acc.z = fmaf(w1, v1.z, acc.z); acc.w = fmaf(w1, v1.w, acc.w);
        acc.x = fmaf(w2, v2.x, acc.x); acc.y = fmaf(w2, v2.y, acc.y);
        acc.z = fmaf(w2, v2.z, acc.z); acc.w = fmaf(w2, v2.w, acc.w);
        acc.x = fmaf(w3, v3.x, acc.x); acc.y = fmaf(w3, v3.y, acc.y);
        acc.z = fmaf(w3, v3.z, acc.z); acc.w = fmaf(w3, v3.w, acc.w);
        acc.x = fmaf(w4, v4.x, acc.x); acc.y = fmaf(w4, v4.y, acc.y);
        acc.z = fmaf(w4, v4.z, acc.z); acc.w = fmaf(w4, v4.w, acc.w);
        acc.x = fmaf(w5, v5.x, acc.x); acc.y = fmaf(w5, v5.y, acc.y);
        acc.z = fmaf(w5, v5.z, acc.z); acc.w = fmaf(w5, v5.w, acc.w);
        acc.x = fmaf(w6, v6.x, acc.x); acc.y = fmaf(w6, v6.y, acc.y);
        acc.z = fmaf(w6, v6.z, acc.z); acc.w = fmaf(w6, v6.w, acc.w);
        acc.x = fmaf(w7, v7.x, acc.x); acc.y = fmaf(w7, v7.y, acc.y);
        acc.z = fmaf(w7, v7.z, acc.z); acc.w = fmaf(w7, v7.w, acc.w);

        *op = acc;
    }
}

extern "C" void kernel_launch(void* const* d_in, const int* in_sizes, int n_in,
                              void* d_out, int out_size) {
    const float4* f4  = (const float4*)d_in[0];
    const float* kern = (const float*)d_in[1];
    float4* o4        = (float4*)d_out;

    dim3 grid(NGRP_ * GRPW_);   // 1184 CTAs = one resident wave on 148 SMs
    dynhead_1x1_stripe16<<<grid, TPB_>>>(f4, kern, o4);
}

// round 10
// speedup vs baseline: 1.0130x; 1.0130x over previous
#include <cuda_runtime.h>

// DynamicHead: per-sample grouped 1x1 conv (KERNEL_SIZE=1, PAD=0).
// f:      [B=8, C=400, H=128, W=128] fp32   (210 MB, read exactly once)
// kernel: [B=8, N=50, CPG=8]         fp32   (12.8 KB)
// out:    [B=8, N=50, H=128, W=128]  fp32   (26 MB, written once)
//
// R9: R7's winning burst geometry (8 sub-CTAs per (b,n) group, 8KB
// contiguous per plane per visit, 2-iteration dwell) with PERFECT load
// balance: 100 groups x 8 subs = 800 CTAs, each group handles exactly
// 4 bn (stride 100). Eliminates R7's 1.5x imbalance tail and drops
// concurrent plane streams 1216 -> 800. Per-thread structure unchanged:
// 8 independent LDG.128 (MLP=8), default policy, L1-broadcast weights.

#define N_      50
#define HW4_    4096                      // 128*128/4 float4 per plane
#define BN_     400
#define TPB_    256
#define GRPW_   8                         // sub-CTAs per group
#define NGRP_   100                       // 100 groups -> exactly 4 bn each

__global__ __launch_bounds__(TPB_)
void dynhead_1x1_bal(const float4* __restrict__ f4,
                     const float* __restrict__ kern,
                     float4* __restrict__ o4) {
    const int g   = blockIdx.x >> 3;         // group id (0..99)
    const int sub = blockIdx.x & (GRPW_-1);  // 0..7 within group

#pragma unroll
    for (int v = 0; v < 4; v++) {            // exactly 4 bn per group
        const int bn = g + v * NGRP_;
        const int b = bn / N_;
        const int n = bn - b * N_;

        // 8 group weights: warp-uniform, L1 broadcast.
        const float* kp = kern + bn * 8;
        const float w0 = __ldg(kp + 0), w1 = __ldg(kp + 1);
        const float w2 = __ldg(kp + 2), w3 = __ldg(kp + 3);
        const float w4 = __ldg(kp + 4), w5 = __ldg(kp + 5);
        const float w6 = __ldg(kp + 6), w7 = __ldg(kp + 7);

        const float4* __restrict__ fp = f4 + ((b * 400 + n * 8) << 12);
        float4* __restrict__ op = o4 + (bn << 12);

        // sub-CTA owns contiguous pos range [sub*512, (sub+1)*512).
        int pos = sub * 512 + threadIdx.x;
#pragma unroll
        for (int i = 0; i < 2; i++, pos += TPB_) {
            const float4 v0 = fp[0 * HW4_ + pos];
            const float4 v1 = fp[1 * HW4_ + pos];
            const float4 v2 = fp[2 * HW4_ + pos];
            const float4 v3 = fp[3 * HW4_ + pos];
            const float4 v4 = fp[4 * HW4_ + pos];
            const float4 v5 = fp[5 * HW4_ + pos];
            const float4 v6 = fp[6 * HW4_ + pos];
            const float4 v7 = fp[7 * HW4_ + pos];

            float4 acc;
            acc.x = v0.x * w0; acc.y = v0.y * w0; acc.z = v0.z * w0; acc.w = v0.w * w0;
            acc.x = fmaf(w1, v1.x, acc.x); acc.y = fmaf(w1, v1.y, acc.y);
            acc.z = fmaf(w1, v1.z, acc.z); acc.w = fmaf(w1, v1.w, acc.w);
            acc.x = fmaf(w2, v2.x, acc.x); acc.y = fmaf(w2, v2.y, acc.y);
            acc.z = fmaf(w2, v2.z, acc.z); acc.w = fmaf(w2, v2.w, acc.w);
            acc.x = fmaf(w3, v3.x, acc.x); acc.y = fmaf(w3, v3.y, acc.y);
            acc.z = fmaf(w3, v3.z, acc.z); acc.w = fmaf(w3, v3.w, acc.w);
            acc.x = fmaf(w4, v4.x, acc.x); acc.y = fmaf(w4, v4.y, acc.y);
            acc.z = fmaf(w4, v4.z, acc.z); acc.w = fmaf(w4, v4.w, acc.w);
            acc.x = fmaf(w5, v5.x, acc.x); acc.y = fmaf(w5, v5.y, acc.y);
            acc.z = fmaf(w5, v5.z, acc.z); acc.w = fmaf(w5, v5.w, acc.w);
            acc.x = fmaf(w6, v6.x, acc.x); acc.y = fmaf(w6, v6.y, acc.y);
            acc.z = fmaf(w6, v6.z, acc.z); acc.w = fmaf(w6, v6.w, acc.w);
            acc.x = fmaf(w7, v7.x, acc.x); acc.y = fmaf(w7, v7.y, acc.y);
            acc.z = fmaf(w7, v7.z, acc.z); acc.w = fmaf(w7, v7.w, acc.w);

            op[pos] = acc;
        }
    }
}

extern "C" void kernel_launch(void* const* d_in, const int* in_sizes, int n_in,
                              void* d_out, int out_size) {
    const float4* f4  = (const float4*)d_in[0];
    const float* kern = (const float*)d_in[1];
    float4* o4        = (float4*)d_out;

    dim3 grid(NGRP_ * GRPW_);   // 800 CTAs, perfectly balanced (4 bn each)
    dynhead_1x1_bal<<<grid, TPB_>>>(f4, kern, o4);
}